// round 2
// baseline (speedup 1.0000x reference)
#include <cuda_runtime.h>
#include <cuda_bf16.h>

#define NN 50000
#define EE 800000
#define DD 128
#define OUTD 64
#define NG 64

// Scratch (device globals; no allocation allowed)
__device__ float g_agg[NN * DD];
__device__ float g_bufA[NN * DD];
__device__ float g_bufB[NN * DD];
__device__ float g_pool[NG * DD];
__device__ float g_cnt[NG];

// ---------------------------------------------------------------------------
// Zero kernels
// ---------------------------------------------------------------------------
__global__ void zero_agg_kernel() {
    int t = blockIdx.x * blockDim.x + threadIdx.x;
    float4* p = reinterpret_cast<float4*>(g_agg);
    int n4 = NN * DD / 4;
    if (t < n4) p[t] = make_float4(0.f, 0.f, 0.f, 0.f);
}

__global__ void zero_pool_kernel() {
    int t = blockIdx.x * blockDim.x + threadIdx.x;
    if (t < NG * DD) g_pool[t] = 0.f;
    if (t < NG) g_cnt[t] = 0.f;
}

// ---------------------------------------------------------------------------
// Scatter-add: for each edge e, g_agg[dst[e]] += in[src[e]]  (128 floats)
// One warp per edge; each lane handles one float4; red.global.add.v4.f32.
// ---------------------------------------------------------------------------
__global__ void scatter_kernel(const float* __restrict__ in,
                               const int* __restrict__ ei) {
    int t = blockIdx.x * blockDim.x + threadIdx.x;
    int e = t >> 5;
    int lane = t & 31;
    if (e >= EE) return;
    int src = ei[e];
    int dst = ei[EE + e];
    const float4* xr = reinterpret_cast<const float4*>(in + (size_t)src * DD);
    float4 v = xr[lane];
    float* dp = g_agg + (size_t)dst * DD + lane * 4;
    asm volatile("red.global.add.v4.f32 [%0], {%1,%2,%3,%4};"
                 :: "l"(dp), "f"(v.x), "f"(v.y), "f"(v.z), "f"(v.w)
                 : "memory");
}

// ---------------------------------------------------------------------------
// Fused SAGE linear: out = maybe_relu(agg @ Wl^T + b + X @ Wr^T)
// BM=64 rows, BN=128 cols (full), K=128 per phase, two phases (Wl/agg, Wr/X).
// 256 threads; thread tile 4 rows x 8 cols (cols strided by 16 for
// conflict-free smem reads with 129-float row padding on W).
// Dynamic smem: ws[128*129] + as[64*128] floats = 96.5 KB.
// ---------------------------------------------------------------------------
__global__ void sage_gemm_kernel(const float* __restrict__ A,
                                 const float* __restrict__ X,
                                 const float* __restrict__ Wl,
                                 const float* __restrict__ Wr,
                                 const float* __restrict__ bias,
                                 float* __restrict__ out,
                                 int relu) {
    extern __shared__ float smem[];
    float* ws = smem;                 // [128][129]
    float* as = smem + 128 * 129;     // [64][128]

    int tid = threadIdx.x;
    int row0 = blockIdx.x * 64;
    int ty = tid >> 4;   // 0..15 -> rows ty*4 .. ty*4+3
    int tx = tid & 15;   // cols tx + 16*j, j=0..7

    float acc[4][8];
#pragma unroll
    for (int i = 0; i < 4; i++)
#pragma unroll
        for (int j = 0; j < 8; j++) acc[i][j] = 0.f;

    for (int phase = 0; phase < 2; phase++) {
        const float* In = phase ? X : A;
        const float* W = phase ? Wr : Wl;

        // Load W [128 out][128 in] into ws[c*129 + k] (coalesced, conflict-free)
        for (int idx = tid; idx < 128 * 128; idx += 256) {
            int c = idx >> 7;
            int k = idx & 127;
            ws[c * 129 + k] = W[idx];
        }
        // Load A-tile [64][128]
        for (int idx = tid; idx < 64 * 128; idx += 256) {
            int r = idx >> 7;
            int k = idx & 127;
            int row = row0 + r;
            as[idx] = (row < NN) ? In[(size_t)row * DD + k] : 0.f;
        }
        __syncthreads();

#pragma unroll 4
        for (int k = 0; k < 128; k++) {
            float a[4];
#pragma unroll
            for (int i = 0; i < 4; i++) a[i] = as[(ty * 4 + i) * 128 + k];
            float w[8];
#pragma unroll
            for (int j = 0; j < 8; j++) w[j] = ws[(tx + 16 * j) * 129 + k];
#pragma unroll
            for (int i = 0; i < 4; i++)
#pragma unroll
                for (int j = 0; j < 8; j++) acc[i][j] += a[i] * w[j];
        }
        __syncthreads();
    }

#pragma unroll
    for (int i = 0; i < 4; i++) {
        int row = row0 + ty * 4 + i;
        if (row >= NN) continue;
#pragma unroll
        for (int j = 0; j < 8; j++) {
            int c = tx + 16 * j;
            float v = acc[i][j] + bias[c];
            if (relu) v = fmaxf(v, 0.f);
            out[(size_t)row * DD + c] = v;
        }
    }
}

// ---------------------------------------------------------------------------
// Pool: per-node warp does red.add.v4 of its feature row into g_pool[graph]
// ---------------------------------------------------------------------------
__global__ void pool_kernel(const float* __restrict__ h,
                            const int* __restrict__ batch) {
    int t = blockIdx.x * blockDim.x + threadIdx.x;
    int n = t >> 5;
    int lane = t & 31;
    if (n >= NN) return;
    int g = batch[n];
    float4 v = reinterpret_cast<const float4*>(h + (size_t)n * DD)[lane];
    float* dp = g_pool + (size_t)g * DD + lane * 4;
    asm volatile("red.global.add.v4.f32 [%0], {%1,%2,%3,%4};"
                 :: "l"(dp), "f"(v.x), "f"(v.y), "f"(v.z), "f"(v.w)
                 : "memory");
    if (lane == 0) atomicAdd(&g_cnt[g], 1.0f);
}

// ---------------------------------------------------------------------------
// Final: out[g][o] = (pool[g]/max(cnt,1)) . Wlin[o] + blin[o]
// ---------------------------------------------------------------------------
__global__ void final_kernel(const float* __restrict__ Wlin,
                             const float* __restrict__ blin,
                             float* __restrict__ out) {
    int g = blockIdx.x;   // 64 blocks
    int o = threadIdx.x;  // 64 threads
    __shared__ float ps[DD];
    ps[o] = g_pool[g * DD + o];
    ps[o + 64] = g_pool[g * DD + o + 64];
    __syncthreads();
    float inv = 1.f / fmaxf(g_cnt[g], 1.f);
    float dot = 0.f;
#pragma unroll 4
    for (int k = 0; k < DD; k++) dot += ps[k] * Wlin[o * DD + k];
    out[g * OUTD + o] = dot * inv + blin[o];
}

// ---------------------------------------------------------------------------
extern "C" void kernel_launch(void* const* d_in, const int* in_sizes, int n_in,
                              void* d_out, int out_size) {
    const float* x    = (const float*)d_in[0];
    const int*   ei   = (const int*)d_in[1];
    const int*   batch= (const int*)d_in[2];
    const float* W1l  = (const float*)d_in[3];
    const float* b1l  = (const float*)d_in[4];
    const float* W1r  = (const float*)d_in[5];
    const float* W2l  = (const float*)d_in[6];
    const float* b2l  = (const float*)d_in[7];
    const float* W2r  = (const float*)d_in[8];
    const float* W3l  = (const float*)d_in[9];
    const float* b3l  = (const float*)d_in[10];
    const float* W3r  = (const float*)d_in[11];
    const float* Wlin = (const float*)d_in[12];
    const float* blin = (const float*)d_in[13];
    float* out = (float*)d_out;

    static_assert(NN * DD % 4 == 0, "");
    const int smem_gemm = (128 * 129 + 64 * 128) * sizeof(float);
    cudaFuncSetAttribute(sage_gemm_kernel,
                         cudaFuncAttributeMaxDynamicSharedMemorySize, smem_gemm);

    const int zeroBlocks = (NN * DD / 4 + 255) / 256;
    const int scatBlocks = (EE * 32 + 255) / 256;
    const int gemmBlocks = (NN + 63) / 64;
    const int poolBlocks = (NN * 32 + 255) / 256;

    float* devAgg;  cudaGetSymbolAddress((void**)&devAgg, g_agg);
    float* devA;    cudaGetSymbolAddress((void**)&devA, g_bufA);
    float* devB;    cudaGetSymbolAddress((void**)&devB, g_bufB);

    // Layer 1
    zero_agg_kernel<<<zeroBlocks, 256>>>();
    scatter_kernel<<<scatBlocks, 256>>>(x, ei);
    sage_gemm_kernel<<<gemmBlocks, 256, smem_gemm>>>(devAgg, x, W1l, W1r, b1l, devA, 1);
    // Layer 2
    zero_agg_kernel<<<zeroBlocks, 256>>>();
    scatter_kernel<<<scatBlocks, 256>>>(devA, ei);
    sage_gemm_kernel<<<gemmBlocks, 256, smem_gemm>>>(devAgg, devA, W2l, W2r, b2l, devB, 1);
    // Layer 3
    zero_agg_kernel<<<zeroBlocks, 256>>>();
    scatter_kernel<<<scatBlocks, 256>>>(devB, ei);
    sage_gemm_kernel<<<gemmBlocks, 256, smem_gemm>>>(devAgg, devB, W3l, W3r, b3l, devA, 0);
    // Pool + final linear
    zero_pool_kernel<<<(NG * DD + 255) / 256, 256>>>();
    pool_kernel<<<poolBlocks, 256>>>(devA, batch);
    final_kernel<<<NG, OUTD>>>(Wlin, blin, out);
}

// round 3
// speedup vs baseline: 1.5521x; 1.5521x over previous
#include <cuda_runtime.h>
#include <cuda_bf16.h>

#define NN 50000
#define EE 800000
#define DD 128
#define OUTD 64
#define NG 64

// Scratch (device globals; no allocation allowed)
__device__ float g_agg[NN * DD];
__device__ float g_bufA[NN * DD];
__device__ float g_bufB[NN * DD];
__device__ float g_pool[NG * DD];
__device__ float g_cnt[NG];
__device__ int   g_deg[NN];        // degree counts, then reused as fill cursor
__device__ int   g_rowptr[NN + 1];
__device__ int   g_csr[EE];        // src node ids grouped by dst

// ---------------------------------------------------------------------------
// CSR build
// ---------------------------------------------------------------------------
__global__ void zero_deg_kernel() {
    int t = blockIdx.x * blockDim.x + threadIdx.x;
    if (t < NN) g_deg[t] = 0;
}

__global__ void count_deg_kernel(const int* __restrict__ ei) {
    int e = blockIdx.x * blockDim.x + threadIdx.x;
    if (e < EE) atomicAdd(&g_deg[ei[EE + e]], 1);
}

// Single-block exclusive scan of g_deg -> g_rowptr. 1024 threads, ~49 elems each.
__global__ void scan_kernel() {
    const int CH = (NN + 1023) / 1024;
    int t = threadIdx.x;
    int beg = t * CH;
    int end = min(beg + CH, NN);
    int sum = 0;
    for (int i = beg; i < end; i++) sum += g_deg[i];

    __shared__ int s[1024];
    s[t] = sum;
    __syncthreads();
    for (int off = 1; off < 1024; off <<= 1) {
        int v = (t >= off) ? s[t - off] : 0;
        __syncthreads();
        s[t] += v;
        __syncthreads();
    }
    int run = s[t] - sum;  // exclusive prefix
    for (int i = beg; i < end; i++) {
        g_rowptr[i] = run;
        run += g_deg[i];
    }
    if (t == 1023) g_rowptr[NN] = s[1023];
}

__global__ void fill_csr_kernel(const int* __restrict__ ei) {
    int e = blockIdx.x * blockDim.x + threadIdx.x;
    if (e >= EE) return;
    int d = ei[EE + e];
    int slot = atomicAdd(&g_deg[d], 1);
    g_csr[g_rowptr[d] + slot] = ei[e];
}

// ---------------------------------------------------------------------------
// Gather-aggregate: warp per destination node; lane owns one float4 (16B).
// agg[n] = sum_{s in neighbors(n)} in[s]
// ---------------------------------------------------------------------------
__global__ void gather_kernel(const float* __restrict__ in,
                              float* __restrict__ agg) {
    int w = (blockIdx.x * blockDim.x + threadIdx.x) >> 5;
    int lane = threadIdx.x & 31;
    if (w >= NN) return;
    int beg = g_rowptr[w];
    int end = g_rowptr[w + 1];

    float4 a0 = make_float4(0.f, 0.f, 0.f, 0.f);
    float4 a1 = make_float4(0.f, 0.f, 0.f, 0.f);
    int i = beg;
    for (; i + 1 < end; i += 2) {
        int s0 = g_csr[i];
        int s1 = g_csr[i + 1];
        float4 v0 = reinterpret_cast<const float4*>(in + (size_t)s0 * DD)[lane];
        float4 v1 = reinterpret_cast<const float4*>(in + (size_t)s1 * DD)[lane];
        a0.x += v0.x; a0.y += v0.y; a0.z += v0.z; a0.w += v0.w;
        a1.x += v1.x; a1.y += v1.y; a1.z += v1.z; a1.w += v1.w;
    }
    if (i < end) {
        int s0 = g_csr[i];
        float4 v0 = reinterpret_cast<const float4*>(in + (size_t)s0 * DD)[lane];
        a0.x += v0.x; a0.y += v0.y; a0.z += v0.z; a0.w += v0.w;
    }
    a0.x += a1.x; a0.y += a1.y; a0.z += a1.z; a0.w += a1.w;
    reinterpret_cast<float4*>(agg + (size_t)w * DD)[lane] = a0;
}

// ---------------------------------------------------------------------------
// Fused SAGE linear v2: out = maybe_relu(agg @ Wl^T + b + X @ Wr^T)
// BM=64 rows, BN=128 cols, K=128 per phase, two phases.
// Transposed (k-major) smem tiles, vectorized LDS.128 inner loop:
//   per thread per k: 1 LDS.128 (A frag, 4 rows) + 2 LDS.128 (W frag, 8 cols)
//   + 32 FFMA. 256 threads, thread tile 4x8.
// smem: asT[128][68] + wsT[128][132] floats = 100.0 KB -> 2 blocks/SM.
// ---------------------------------------------------------------------------
#define AP 68   // A-tile row pad (16B aligned, odd/4 for bank spread)
#define WP 132  // W-tile row pad (16B aligned)

__global__ __launch_bounds__(256, 2)
void sage_gemm2_kernel(const float* __restrict__ A,
                       const float* __restrict__ X,
                       const float* __restrict__ Wl,
                       const float* __restrict__ Wr,
                       const float* __restrict__ bias,
                       float* __restrict__ out,
                       int relu) {
    extern __shared__ float smem[];
    float* asT = smem;                // [128][AP]  k-major A tile (64 rows)
    float* wsT = smem + 128 * AP;     // [128][WP]  k-major W tile (128 cols)

    int tid = threadIdx.x;
    int row0 = blockIdx.x * 64;
    int ty = tid >> 4;    // 0..15 -> rows m0 = ty*4
    int tx = tid & 15;    // cols n0 = tx*8
    int m0 = ty * 4;
    int n0 = tx * 8;

    float acc[4][8];
#pragma unroll
    for (int i = 0; i < 4; i++)
#pragma unroll
        for (int j = 0; j < 8; j++) acc[i][j] = 0.f;

    for (int phase = 0; phase < 2; phase++) {
        const float* In = phase ? X : A;
        const float* W = phase ? Wr : Wl;

        // A tile: In[row0+m][k] -> asT[k][m]  (coalesced LDG, strided STS)
        for (int idx = tid; idx < 64 * 128; idx += 256) {
            int m = idx >> 7;
            int k = idx & 127;
            int row = row0 + m;
            float v = (row < NN) ? In[(size_t)row * DD + k] : 0.f;
            asT[k * AP + m] = v;
        }
        // W tile: W[n][k] -> wsT[k][n]
        for (int idx = tid; idx < 128 * 128; idx += 256) {
            int n = idx >> 7;
            int k = idx & 127;
            wsT[k * WP + n] = W[idx];
        }
        __syncthreads();

#pragma unroll 8
        for (int k = 0; k < 128; k++) {
            float4 av = *reinterpret_cast<const float4*>(&asT[k * AP + m0]);
            float4 w0 = *reinterpret_cast<const float4*>(&wsT[k * WP + n0]);
            float4 w1 = *reinterpret_cast<const float4*>(&wsT[k * WP + n0 + 4]);
            float a[4] = {av.x, av.y, av.z, av.w};
            float w[8] = {w0.x, w0.y, w0.z, w0.w, w1.x, w1.y, w1.z, w1.w};
#pragma unroll
            for (int i = 0; i < 4; i++)
#pragma unroll
                for (int j = 0; j < 8; j++) acc[i][j] += a[i] * w[j];
        }
        __syncthreads();
    }

    float b[8];
#pragma unroll
    for (int j = 0; j < 8; j++) b[j] = bias[n0 + j];

#pragma unroll
    for (int i = 0; i < 4; i++) {
        int row = row0 + m0 + i;
        if (row >= NN) continue;
        float4 o0, o1;
        float v0 = acc[i][0] + b[0], v1 = acc[i][1] + b[1];
        float v2 = acc[i][2] + b[2], v3 = acc[i][3] + b[3];
        float v4 = acc[i][4] + b[4], v5 = acc[i][5] + b[5];
        float v6 = acc[i][6] + b[6], v7 = acc[i][7] + b[7];
        if (relu) {
            v0 = fmaxf(v0, 0.f); v1 = fmaxf(v1, 0.f); v2 = fmaxf(v2, 0.f); v3 = fmaxf(v3, 0.f);
            v4 = fmaxf(v4, 0.f); v5 = fmaxf(v5, 0.f); v6 = fmaxf(v6, 0.f); v7 = fmaxf(v7, 0.f);
        }
        o0 = make_float4(v0, v1, v2, v3);
        o1 = make_float4(v4, v5, v6, v7);
        float4* op = reinterpret_cast<float4*>(out + (size_t)row * DD + n0);
        op[0] = o0;
        op[1] = o1;
    }
}

// ---------------------------------------------------------------------------
// Pool + final linear
// ---------------------------------------------------------------------------
__global__ void zero_pool_kernel() {
    int t = blockIdx.x * blockDim.x + threadIdx.x;
    if (t < NG * DD) g_pool[t] = 0.f;
    if (t < NG) g_cnt[t] = 0.f;
}

__global__ void pool_kernel(const float* __restrict__ h,
                            const int* __restrict__ batch) {
    int t = blockIdx.x * blockDim.x + threadIdx.x;
    int n = t >> 5;
    int lane = t & 31;
    if (n >= NN) return;
    int g = batch[n];
    float4 v = reinterpret_cast<const float4*>(h + (size_t)n * DD)[lane];
    float* dp = g_pool + (size_t)g * DD + lane * 4;
    asm volatile("red.global.add.v4.f32 [%0], {%1,%2,%3,%4};"
                 :: "l"(dp), "f"(v.x), "f"(v.y), "f"(v.z), "f"(v.w)
                 : "memory");
    if (lane == 0) atomicAdd(&g_cnt[g], 1.0f);
}

__global__ void final_kernel(const float* __restrict__ Wlin,
                             const float* __restrict__ blin,
                             float* __restrict__ out) {
    int g = blockIdx.x;   // 64 blocks
    int o = threadIdx.x;  // 64 threads
    __shared__ float ps[DD];
    ps[o] = g_pool[g * DD + o];
    ps[o + 64] = g_pool[g * DD + o + 64];
    __syncthreads();
    float inv = 1.f / fmaxf(g_cnt[g], 1.f);
    float dot = 0.f;
#pragma unroll 4
    for (int k = 0; k < DD; k++) dot += ps[k] * Wlin[o * DD + k];
    out[g * OUTD + o] = dot * inv + blin[o];
}

// ---------------------------------------------------------------------------
extern "C" void kernel_launch(void* const* d_in, const int* in_sizes, int n_in,
                              void* d_out, int out_size) {
    const float* x    = (const float*)d_in[0];
    const int*   ei   = (const int*)d_in[1];
    const int*   batch= (const int*)d_in[2];
    const float* W1l  = (const float*)d_in[3];
    const float* b1l  = (const float*)d_in[4];
    const float* W1r  = (const float*)d_in[5];
    const float* W2l  = (const float*)d_in[6];
    const float* b2l  = (const float*)d_in[7];
    const float* W2r  = (const float*)d_in[8];
    const float* W3l  = (const float*)d_in[9];
    const float* b3l  = (const float*)d_in[10];
    const float* W3r  = (const float*)d_in[11];
    const float* Wlin = (const float*)d_in[12];
    const float* blin = (const float*)d_in[13];
    float* out = (float*)d_out;

    const int smem_gemm = (128 * AP + 128 * WP) * sizeof(float);
    cudaFuncSetAttribute(sage_gemm2_kernel,
                         cudaFuncAttributeMaxDynamicSharedMemorySize, smem_gemm);

    const int nodeBlocks = (NN + 255) / 256;
    const int edgeBlocks = (EE + 255) / 256;
    const int gatherBlocks = (NN * 32 + 255) / 256;
    const int gemmBlocks = (NN + 63) / 64;
    const int poolBlocks = (NN * 32 + 255) / 256;

    float* devAgg;  cudaGetSymbolAddress((void**)&devAgg, g_agg);
    float* devA;    cudaGetSymbolAddress((void**)&devA, g_bufA);
    float* devB;    cudaGetSymbolAddress((void**)&devB, g_bufB);

    // Build CSR (dst-grouped) once; reused by all 3 layers.
    zero_deg_kernel<<<nodeBlocks, 256>>>();
    count_deg_kernel<<<edgeBlocks, 256>>>(ei);
    scan_kernel<<<1, 1024>>>();
    zero_deg_kernel<<<nodeBlocks, 256>>>();   // reset cursors
    fill_csr_kernel<<<edgeBlocks, 256>>>(ei);

    // Layer 1
    gather_kernel<<<gatherBlocks, 256>>>(x, devAgg);
    sage_gemm2_kernel<<<gemmBlocks, 256, smem_gemm>>>(devAgg, x, W1l, W1r, b1l, devA, 1);
    // Layer 2
    gather_kernel<<<gatherBlocks, 256>>>(devA, devAgg);
    sage_gemm2_kernel<<<gemmBlocks, 256, smem_gemm>>>(devAgg, devA, W2l, W2r, b2l, devB, 1);
    // Layer 3
    gather_kernel<<<gatherBlocks, 256>>>(devB, devAgg);
    sage_gemm2_kernel<<<gemmBlocks, 256, smem_gemm>>>(devAgg, devB, W3l, W3r, b3l, devA, 0);
    // Pool + final linear
    zero_pool_kernel<<<(NG * DD + 255) / 256, 256>>>();
    pool_kernel<<<poolBlocks, 256>>>(devA, batch);
    final_kernel<<<NG, OUTD>>>(Wlin, blin, out);
}

// round 9
// speedup vs baseline: 2.8388x; 1.8290x over previous
#include <cuda_runtime.h>
#include <cuda_bf16.h>
#include <cstdint>

#define NN 50000
#define EE 800000
#define DD 128
#define OUTD 64
#define NG 64

// Scratch (device globals; no allocation allowed)
__device__ float g_agg[NN * DD];
__device__ float g_bufA[NN * DD];
__device__ float g_bufB[NN * DD];
__device__ float g_pool[NG * DD];
__device__ float g_cnt[NG];
__device__ int   g_deg[NN];
__device__ int   g_rowptr[NN + 1];
__device__ int   g_csr[EE];

// ===========================================================================
// CSR build
// ===========================================================================
__global__ void zero_deg_kernel() {
    int t = blockIdx.x * blockDim.x + threadIdx.x;
    if (t < NN) g_deg[t] = 0;
}
__global__ void count_deg_kernel(const int* __restrict__ ei) {
    int e = blockIdx.x * blockDim.x + threadIdx.x;
    if (e < EE) atomicAdd(&g_deg[ei[EE + e]], 1);
}
__global__ void scan_kernel() {
    const int CH = (NN + 1023) / 1024;
    int t = threadIdx.x;
    int beg = t * CH;
    int end = min(beg + CH, NN);
    int sum = 0;
    for (int i = beg; i < end; i++) sum += g_deg[i];
    __shared__ int s[1024];
    s[t] = sum;
    __syncthreads();
    for (int off = 1; off < 1024; off <<= 1) {
        int v = (t >= off) ? s[t - off] : 0;
        __syncthreads();
        s[t] += v;
        __syncthreads();
    }
    int run = s[t] - sum;
    for (int i = beg; i < end; i++) {
        g_rowptr[i] = run;
        run += g_deg[i];
    }
    if (t == 1023) g_rowptr[NN] = s[1023];
}
__global__ void fill_csr_kernel(const int* __restrict__ ei) {
    int e = blockIdx.x * blockDim.x + threadIdx.x;
    if (e >= EE) return;
    int d = ei[EE + e];
    int slot = atomicAdd(&g_deg[d], 1);
    g_csr[g_rowptr[d] + slot] = ei[e];
}

// ===========================================================================
// Gather-aggregate (CSR): warp per dst node, lane owns one float4
// ===========================================================================
__global__ void gather_kernel(const float* __restrict__ in,
                              float* __restrict__ agg) {
    int w = (blockIdx.x * blockDim.x + threadIdx.x) >> 5;
    int lane = threadIdx.x & 31;
    if (w >= NN) return;
    int beg = g_rowptr[w];
    int end = g_rowptr[w + 1];
    float4 a0 = make_float4(0.f, 0.f, 0.f, 0.f);
    float4 a1 = make_float4(0.f, 0.f, 0.f, 0.f);
    int i = beg;
    for (; i + 1 < end; i += 2) {
        int s0 = g_csr[i];
        int s1 = g_csr[i + 1];
        float4 v0 = reinterpret_cast<const float4*>(in + (size_t)s0 * DD)[lane];
        float4 v1 = reinterpret_cast<const float4*>(in + (size_t)s1 * DD)[lane];
        a0.x += v0.x; a0.y += v0.y; a0.z += v0.z; a0.w += v0.w;
        a1.x += v1.x; a1.y += v1.y; a1.z += v1.z; a1.w += v1.w;
    }
    if (i < end) {
        int s0 = g_csr[i];
        float4 v0 = reinterpret_cast<const float4*>(in + (size_t)s0 * DD)[lane];
        a0.x += v0.x; a0.y += v0.y; a0.z += v0.z; a0.w += v0.w;
    }
    a0.x += a1.x; a0.y += a1.y; a0.z += a1.z; a0.w += a1.w;
    reinterpret_cast<float4*>(agg + (size_t)w * DD)[lane] = a0;
}

// ===========================================================================
// Split-bf16 mma.sync SAGE GEMM
//   out[128-row tile] = maybe_relu(agg @ Wl^T + b + X @ Wr^T)
// fp32 = hi(bf16) + lo(bf16); D += Ah@Wh + Ah@Wl + Al@Wh (rel err ~1e-5).
// m16n8k16 fragments read k-pairs directly from row-major bf16 smem tiles
// with 272-byte row stride (conflict-free: bank = 4*row + (lane&3)).
// ===========================================================================
#define SP_B 272                     // smem row stride bytes (136 bf16)
#define TILE_B (128 * SP_B)          // 34816 bytes per tile buffer
#define SM_BIAS 0                    // 512 bytes
#define SM_AH   1024
#define SM_AL   (SM_AH + TILE_B)
#define SM_WH   (SM_AL + TILE_B)
#define SM_WL   (SM_WH + TILE_B)
#define SM_TOTAL (SM_WL + TILE_B)

__device__ __forceinline__ void mma_bf16(float* c, const uint32_t* a,
                                         uint32_t b0, uint32_t b1) {
    asm volatile(
        "mma.sync.aligned.m16n8k16.row.col.f32.bf16.bf16.f32 "
        "{%0,%1,%2,%3}, {%4,%5,%6,%7}, {%8,%9}, {%0,%1,%2,%3};"
        : "+f"(c[0]), "+f"(c[1]), "+f"(c[2]), "+f"(c[3])
        : "r"(a[0]), "r"(a[1]), "r"(a[2]), "r"(a[3]), "r"(b0), "r"(b1));
}

// Convert a 128x128 fp32 tile into hi/lo bf16 smem tiles (row-major, SP_B).
__device__ __forceinline__ void convert_tile(const float* __restrict__ src,
                                             int row0, int nrows,
                                             char* dstH, char* dstL, int tid) {
    for (int idx = tid; idx < 128 * 32; idx += 256) {
        int r = idx >> 5;
        int k4 = (idx & 31) << 2;
        float4 v;
        if (row0 + r < nrows)
            v = *reinterpret_cast<const float4*>(src + (size_t)(row0 + r) * DD + k4);
        else
            v = make_float4(0.f, 0.f, 0.f, 0.f);
        __nv_bfloat16 h0 = __float2bfloat16(v.x);
        __nv_bfloat16 h1 = __float2bfloat16(v.y);
        __nv_bfloat16 h2 = __float2bfloat16(v.z);
        __nv_bfloat16 h3 = __float2bfloat16(v.w);
        __nv_bfloat16 l0 = __float2bfloat16(v.x - __bfloat162float(h0));
        __nv_bfloat16 l1 = __float2bfloat16(v.y - __bfloat162float(h1));
        __nv_bfloat16 l2 = __float2bfloat16(v.z - __bfloat162float(h2));
        __nv_bfloat16 l3 = __float2bfloat16(v.w - __bfloat162float(h3));
        uint2 hv, lv;
        hv.x = ((uint32_t)__bfloat16_as_ushort(h1) << 16) | __bfloat16_as_ushort(h0);
        hv.y = ((uint32_t)__bfloat16_as_ushort(h3) << 16) | __bfloat16_as_ushort(h2);
        lv.x = ((uint32_t)__bfloat16_as_ushort(l1) << 16) | __bfloat16_as_ushort(l0);
        lv.y = ((uint32_t)__bfloat16_as_ushort(l3) << 16) | __bfloat16_as_ushort(l2);
        uint32_t off = (uint32_t)(r * SP_B + k4 * 2);
        *reinterpret_cast<uint2*>(dstH + off) = hv;
        *reinterpret_cast<uint2*>(dstL + off) = lv;
    }
}

__global__ __launch_bounds__(256, 1)
void sage_gemm_mma_kernel(const float* __restrict__ A,
                          const float* __restrict__ X,
                          const float* __restrict__ Wl,
                          const float* __restrict__ Wr,
                          const float* __restrict__ bias,
                          float* __restrict__ out,
                          int relu) {
    extern __shared__ char smem[];
    char* sAH = smem + SM_AH;
    char* sAL = smem + SM_AL;
    char* sWH = smem + SM_WH;
    char* sWL = smem + SM_WL;
    float* bs = (float*)(smem + SM_BIAS);

    int tid = threadIdx.x;
    int wid = tid >> 5;
    int lane = tid & 31;
    int wr = wid & 3;    // row group: rows wr*32 .. +32
    int wc = wid >> 2;   // col group: cols wc*64 .. +64
    int gr = lane >> 2;          // 0..7
    int ko = (lane & 3) << 2;    // k byte offset within 32B k-step

    int row0 = blockIdx.x * 128;
    if (tid < 128) bs[tid] = bias[tid];

    float acc[2][8][4];
#pragma unroll
    for (int mf = 0; mf < 2; mf++)
#pragma unroll
        for (int nf = 0; nf < 8; nf++)
#pragma unroll
            for (int q = 0; q < 4; q++) acc[mf][nf][q] = 0.f;

    for (int phase = 0; phase < 2; phase++) {
        const float* In = phase ? X : A;
        const float* W = phase ? Wr : Wl;
        if (phase) __syncthreads();  // previous phase's MMAs done before overwrite
        convert_tile(In, row0, NN, sAH, sAL, tid);
        convert_tile(W, 0, 128, sWH, sWL, tid);
        __syncthreads();

        const char* pa0 = sAH + (wr * 32 + gr) * SP_B + ko;
        const char* pl0 = sAL + (wr * 32 + gr) * SP_B + ko;
        const char* pbh = sWH + (wc * 64 + gr) * SP_B + ko;
        const char* pbl = sWL + (wc * 64 + gr) * SP_B + ko;

#pragma unroll
        for (int ks = 0; ks < 8; ks++) {
            int kb = ks * 32;
            uint32_t ah[2][4], al[2][4];
#pragma unroll
            for (int mf = 0; mf < 2; mf++) {
                const char* pa = pa0 + mf * 16 * SP_B + kb;
                ah[mf][0] = *(const uint32_t*)(pa);
                ah[mf][1] = *(const uint32_t*)(pa + 8 * SP_B);
                ah[mf][2] = *(const uint32_t*)(pa + 16);
                ah[mf][3] = *(const uint32_t*)(pa + 8 * SP_B + 16);
                const char* pl = pl0 + mf * 16 * SP_B + kb;
                al[mf][0] = *(const uint32_t*)(pl);
                al[mf][1] = *(const uint32_t*)(pl + 8 * SP_B);
                al[mf][2] = *(const uint32_t*)(pl + 16);
                al[mf][3] = *(const uint32_t*)(pl + 8 * SP_B + 16);
            }
#pragma unroll
            for (int nf = 0; nf < 8; nf++) {
                const char* ph = pbh + nf * 8 * SP_B + kb;
                uint32_t bh0 = *(const uint32_t*)(ph);
                uint32_t bh1 = *(const uint32_t*)(ph + 16);
                const char* pw = pbl + nf * 8 * SP_B + kb;
                uint32_t bl0 = *(const uint32_t*)(pw);
                uint32_t bl1 = *(const uint32_t*)(pw + 16);
                mma_bf16(acc[0][nf], ah[0], bh0, bh1);
                mma_bf16(acc[1][nf], ah[1], bh0, bh1);
                mma_bf16(acc[0][nf], al[0], bh0, bh1);
                mma_bf16(acc[1][nf], al[1], bh0, bh1);
                mma_bf16(acc[0][nf], ah[0], bl0, bl1);
                mma_bf16(acc[1][nf], ah[1], bl0, bl1);
            }
        }
    }

    // Epilogue: C thread map: rows (gr, gr+8) of each 16-row mfrag,
    // cols 2*(lane&3)+{0,1} of each 8-col nfrag.
    int crow0 = row0 + wr * 32;
    int ccol0 = wc * 64 + ((lane & 3) << 1);
#pragma unroll
    for (int mf = 0; mf < 2; mf++) {
#pragma unroll
        for (int half = 0; half < 2; half++) {
            int row = crow0 + mf * 16 + gr + half * 8;
            if (row >= NN) continue;
#pragma unroll
            for (int nf = 0; nf < 8; nf++) {
                int col = ccol0 + nf * 8;
                float v0 = acc[mf][nf][half * 2 + 0] + bs[col];
                float v1 = acc[mf][nf][half * 2 + 1] + bs[col + 1];
                if (relu) { v0 = fmaxf(v0, 0.f); v1 = fmaxf(v1, 0.f); }
                *reinterpret_cast<float2*>(out + (size_t)row * DD + col) =
                    make_float2(v0, v1);
            }
        }
    }
}

// ===========================================================================
// Pool + final linear
// ===========================================================================
__global__ void zero_pool_kernel() {
    int t = blockIdx.x * blockDim.x + threadIdx.x;
    if (t < NG * DD) g_pool[t] = 0.f;
    if (t < NG) g_cnt[t] = 0.f;
}
__global__ void pool_kernel(const float* __restrict__ h,
                            const int* __restrict__ batch) {
    int t = blockIdx.x * blockDim.x + threadIdx.x;
    int n = t >> 5;
    int lane = t & 31;
    if (n >= NN) return;
    int g = batch[n];
    float4 v = reinterpret_cast<const float4*>(h + (size_t)n * DD)[lane];
    float* dp = g_pool + (size_t)g * DD + lane * 4;
    asm volatile("red.global.add.v4.f32 [%0], {%1,%2,%3,%4};"
                 :: "l"(dp), "f"(v.x), "f"(v.y), "f"(v.z), "f"(v.w) : "memory");
    if (lane == 0) atomicAdd(&g_cnt[g], 1.0f);
}
__global__ void final_kernel(const float* __restrict__ Wlin,
                             const float* __restrict__ blin,
                             float* __restrict__ out) {
    int g = blockIdx.x;
    int o = threadIdx.x;
    __shared__ float ps[DD];
    ps[o] = g_pool[g * DD + o];
    ps[o + 64] = g_pool[g * DD + o + 64];
    __syncthreads();
    float inv = 1.f / fmaxf(g_cnt[g], 1.f);
    float dot = 0.f;
#pragma unroll 4
    for (int k = 0; k < DD; k++) dot += ps[k] * Wlin[o * DD + k];
    out[g * OUTD + o] = dot * inv + blin[o];
}

// ===========================================================================
extern "C" void kernel_launch(void* const* d_in, const int* in_sizes, int n_in,
                              void* d_out, int out_size) {
    const float* x    = (const float*)d_in[0];
    const int*   ei   = (const int*)d_in[1];
    const int*   batch= (const int*)d_in[2];
    const float* W1l  = (const float*)d_in[3];
    const float* b1l  = (const float*)d_in[4];
    const float* W1r  = (const float*)d_in[5];
    const float* W2l  = (const float*)d_in[6];
    const float* b2l  = (const float*)d_in[7];
    const float* W2r  = (const float*)d_in[8];
    const float* W3l  = (const float*)d_in[9];
    const float* b3l  = (const float*)d_in[10];
    const float* W3r  = (const float*)d_in[11];
    const float* Wlin = (const float*)d_in[12];
    const float* blin = (const float*)d_in[13];
    float* out = (float*)d_out;

    cudaFuncSetAttribute(sage_gemm_mma_kernel,
                         cudaFuncAttributeMaxDynamicSharedMemorySize, SM_TOTAL);

    const int nodeBlocks = (NN + 255) / 256;
    const int edgeBlocks = (EE + 255) / 256;
    const int gatherBlocks = (NN * 32 + 255) / 256;
    const int gemmBlocks = (NN + 127) / 128;
    const int poolBlocks = (NN * 32 + 255) / 256;

    float* devAgg;  cudaGetSymbolAddress((void**)&devAgg, g_agg);
    float* devA;    cudaGetSymbolAddress((void**)&devA, g_bufA);
    float* devB;    cudaGetSymbolAddress((void**)&devB, g_bufB);

    // Build CSR (dst-grouped) once; reused by all 3 layers.
    zero_deg_kernel<<<nodeBlocks, 256>>>();
    count_deg_kernel<<<edgeBlocks, 256>>>(ei);
    scan_kernel<<<1, 1024>>>();
    zero_deg_kernel<<<nodeBlocks, 256>>>();
    fill_csr_kernel<<<edgeBlocks, 256>>>(ei);

    // Layer 1
    gather_kernel<<<gatherBlocks, 256>>>(x, devAgg);
    sage_gemm_mma_kernel<<<gemmBlocks, 256, SM_TOTAL>>>(devAgg, x, W1l, W1r, b1l, devA, 1);
    // Layer 2
    gather_kernel<<<gatherBlocks, 256>>>(devA, devAgg);
    sage_gemm_mma_kernel<<<gemmBlocks, 256, SM_TOTAL>>>(devAgg, devA, W2l, W2r, b2l, devB, 1);
    // Layer 3
    gather_kernel<<<gatherBlocks, 256>>>(devB, devAgg);
    sage_gemm_mma_kernel<<<gemmBlocks, 256, SM_TOTAL>>>(devAgg, devB, W3l, W3r, b3l, devA, 0);
    // Pool + final linear
    zero_pool_kernel<<<(NG * DD + 255) / 256, 256>>>();
    pool_kernel<<<poolBlocks, 256>>>(devA, batch);
    final_kernel<<<NG, OUTD>>>(Wlin, blin, out);
}